// round 7
// baseline (speedup 1.0000x reference)
#include <cuda_runtime.h>
#include <cuda_bf16.h>
#include <cstdint>

// ============================================================================
// Mean-field CRF on GB300 (plain sm_103 PTX; mma.sync m16n8k16 bf16).
// K_sp/K_bl symmetric 8192^2, built once (row-major bf16, upper 256-blocks
// only). Per iteration: k_soft writes P fragments once; k_gemm CTAs own block
// pairs (p<=q), read K[P,Q] once via smem, emit forward (ldmatrix) AND mirror
// (ldmatrix.trans) contributions -> K DRAM traffic halved.
//   q = unaries + (A_sp p) K_sp + (A_bl p) K_bl,  A_* = -(compat @ W_*)
// ============================================================================

#define DI __device__ __forceinline__

static constexpr int   NPT   = 8192;
static constexpr int   NC    = 10;
static constexpr int   CP    = 16;
static constexpr int   NBLK  = 32;            // 256-point blocks
static constexpr int   NPAIR = NBLK * (NBLK + 1) / 2;   // 528
static constexpr float LOG2E = 1.4426950408889634f;
static constexpr float ESP   = LOG2E / 64.0f;
static constexpr float EBL   = LOG2E;

// ---- static device scratch --------------------------------------------------
__device__ __align__(1024) __nv_bfloat16 g_Ksp[(size_t)NPT * NPT]; // row-major
__device__ __align__(1024) __nv_bfloat16 g_Kbl[(size_t)NPT * NPT];
__device__ __align__(1024) uint4 g_PF[2][512][32];   // A-fragments per k16 step
__device__ __align__(256)  float g_part[2][(size_t)NBLK * CP * NPT];
__device__ float g_hsp[NPT], g_hbl[NPT];
__device__ float g_Asp[NC * NC], g_Abl[NC * NC];

DI float ex2f(float x) { float y; asm("ex2.approx.f32 %0, %1;" : "=f"(y) : "f"(x)); return y; }
DI uint32_t s2u(const void* p) {
    uint32_t a;
    asm("{ .reg .u64 t; cvta.to.shared.u64 t, %1; cvt.u32.u64 %0, t; }" : "=r"(a) : "l"(p));
    return a;
}
DI void cp16(uint32_t s, const void* g) {
    asm volatile("cp.async.cg.shared.global [%0], [%1], 16;" :: "r"(s), "l"(g));
}
DI void cp_commit_waitall() {
    asm volatile("cp.async.commit_group;\n\tcp.async.wait_all;" ::: "memory");
}
DI void mma16816(float* c, const uint32_t* a, uint32_t b0, uint32_t b1) {
    asm volatile(
        "mma.sync.aligned.m16n8k16.row.col.f32.bf16.bf16.f32 "
        "{%0,%1,%2,%3}, {%4,%5,%6,%7}, {%8,%9}, {%0,%1,%2,%3};"
        : "+f"(c[0]), "+f"(c[1]), "+f"(c[2]), "+f"(c[3])
        : "r"(a[0]), "r"(a[1]), "r"(a[2]), "r"(a[3]), "r"(b0), "r"(b1));
}
DI void ldmx4(uint32_t* r, uint32_t addr) {
    asm volatile("ldmatrix.sync.aligned.m8n8.x4.shared.b16 {%0,%1,%2,%3}, [%4];"
                 : "=r"(r[0]), "=r"(r[1]), "=r"(r[2]), "=r"(r[3]) : "r"(addr));
}
DI void ldmx4t(uint32_t* r, uint32_t addr) {
    asm volatile("ldmatrix.sync.aligned.m8n8.x4.trans.shared.b16 {%0,%1,%2,%3}, [%4];"
                 : "=r"(r[0]), "=r"(r[1]), "=r"(r[2]), "=r"(r[3]) : "r"(addr));
}

// ---------------- tiny prep --------------------------------------------------
__global__ void k_prepA(const float* __restrict__ Wsp, const float* __restrict__ Wbl,
                        const float* __restrict__ Comp) {
    int t = threadIdx.x;
    if (t < NC * NC) {
        int c = t / NC, c2 = t % NC;
        float s1 = 0.f, s2 = 0.f;
        for (int k = 0; k < NC; k++) {
            s1 += Comp[c * NC + k] * Wsp[k * NC + c2];
            s2 += Comp[c * NC + k] * Wbl[k * NC + c2];
        }
        g_Asp[t] = -s1;
        g_Abl[t] = -s2;
    }
}

__global__ void k_norm(const float* __restrict__ feat) {
    int i = blockIdx.x * 256 + threadIdx.x;
    float f0 = feat[i],           f1 = feat[NPT + i],     f2 = feat[2 * NPT + i];
    float f3 = feat[3 * NPT + i], f4 = feat[4 * NPT + i], f5 = feat[5 * NPT + i];
    float n3 = f0 * f0 + f1 * f1 + f2 * f2;
    float n6 = n3 + f3 * f3 + f4 * f4 + f5 * f5;
    g_hsp[i] = 0.5f * ESP * n3;
    g_hbl[i] = 0.5f * EBL * n6;
}

// ---------------- kernel builder: row-major, needed tiles only ---------------
// Keep 128-tile (bi,bj) if bj>=bi, or it lies in a diagonal 256-block.
__global__ __launch_bounds__(256) void k_pairs(const float* __restrict__ feat) {
    int bi = blockIdx.y, bj = blockIdx.x;
    if (!(bj >= bi || (bj == bi - 1 && (bi & 1)))) return;

    __shared__ float sfi[6][128], sfj[6][128], shs[128], shb[128];
    int t = threadIdx.x;
    int i0 = bi * 128, j0 = bj * 128;

    for (int v = t; v < 6 * 128; v += 256) {
        int d = v >> 7, x = v & 127;
        sfi[d][x] = feat[d * NPT + i0 + x];
        sfj[d][x] = feat[d * NPT + j0 + x];
    }
    if (t < 128) { shs[t] = g_hsp[i0 + t]; shb[t] = g_hbl[i0 + t]; }
    __syncthreads();

    int jl = (t & 15) * 8;          // 8 contiguous j
    int it = t >> 4;

    float fj[6][8], hsj[8], hbj[8];
#pragma unroll
    for (int d = 0; d < 6; d++)
#pragma unroll
        for (int u = 0; u < 8; u++) fj[d][u] = sfj[d][jl + u];
#pragma unroll
    for (int u = 0; u < 8; u++) {
        float n3 = fj[0][u] * fj[0][u] + fj[1][u] * fj[1][u] + fj[2][u] * fj[2][u];
        float n6 = n3 + fj[3][u] * fj[3][u] + fj[4][u] * fj[4][u] + fj[5][u] * fj[5][u];
        hsj[u] = 0.5f * ESP * n3;
        hbj[u] = 0.5f * EBL * n6;
    }

#pragma unroll 1
    for (int r = 0; r < 8; r++) {
        int il = it + r * 16;
        float f0 = sfi[0][il], f1 = sfi[1][il], f2 = sfi[2][il];
        float f3 = sfi[3][il], f4 = sfi[4][il], f5 = sfi[5][il];
        float hs = shs[il], hb = shb[il];

        uint32_t ps[4], pb[4];
#pragma unroll
        for (int g2 = 0; g2 < 4; g2++) {
            float vs[2], vb[2];
#pragma unroll
            for (int u2 = 0; u2 < 2; u2++) {
                int u = g2 * 2 + u2;
                float d3 = fmaf(f2, fj[2][u], fmaf(f1, fj[1][u], f0 * fj[0][u]));
                float dh = fmaf(f5, fj[5][u], fmaf(f4, fj[4][u], f3 * fj[3][u]));
                float d6 = d3 + dh;
                vs[u2] = ex2f(fmaf(ESP, d3, -(hs + hsj[u])));
                vb[u2] = ex2f(fmaf(EBL, d6, -(hb + hbj[u])));
            }
            __nv_bfloat162 s2 = __floats2bfloat162_rn(vs[0], vs[1]);
            __nv_bfloat162 b2 = __floats2bfloat162_rn(vb[0], vb[1]);
            ps[g2] = *reinterpret_cast<uint32_t*>(&s2);
            pb[g2] = *reinterpret_cast<uint32_t*>(&b2);
        }
        size_t off = (size_t)(i0 + il) * NPT + j0 + jl;
        *reinterpret_cast<uint4*>(g_Ksp + off) = make_uint4(ps[0], ps[1], ps[2], ps[3]);
        *reinterpret_cast<uint4*>(g_Kbl + off) = make_uint4(pb[0], pb[1], pb[2], pb[3]);
    }
}

// ---------------- softmax + P-fragment writer --------------------------------
// thread handles points 2T, 2T+1 (T = global thread id, 4096 threads).
__global__ __launch_bounds__(128) void k_soft(const float* __restrict__ unaries,
                                              int mode, int rbuf) {
    __shared__ float sW1[NC * NC], sW2[NC * NC];
    int tl = threadIdx.x;
    for (int v = tl; v < NC * NC; v += 128) { sW1[v] = g_Asp[v]; sW2[v] = g_Abl[v]; }
    __syncthreads();

    int T = blockIdx.x * 128 + tl;
    int j = T * 2;

    float q0[NC], q1[NC];
#pragma unroll
    for (int c = 0; c < NC; c++) {
        float2 u = *reinterpret_cast<const float2*>(&unaries[(size_t)c * NPT + j]);
        q0[c] = u.x; q1[c] = u.y;
    }
    if (mode) {
        const float* pb = g_part[rbuf];
#pragma unroll 4
        for (int sl = 0; sl < NBLK; sl++)
#pragma unroll
            for (int c = 0; c < NC; c++) {
                float2 v = *reinterpret_cast<const float2*>(
                    &pb[((size_t)sl * CP + c) * NPT + j]);
                q0[c] += v.x; q1[c] += v.y;
            }
    }
    float p0[NC], p1[NC];
    float m0 = q0[0], m1 = q1[0];
#pragma unroll
    for (int c = 1; c < NC; c++) { m0 = fmaxf(m0, q0[c]); m1 = fmaxf(m1, q1[c]); }
    float s0 = 0.f, s1 = 0.f;
#pragma unroll
    for (int c = 0; c < NC; c++) {
        p0[c] = ex2f((q0[c] - m0) * LOG2E); s0 += p0[c];
        p1[c] = ex2f((q1[c] - m1) * LOG2E); s1 += p1[c];
    }
    float i0 = __fdividef(1.f, s0), i1 = __fdividef(1.f, s1);
#pragma unroll
    for (int c = 0; c < NC; c++) { p0[c] *= i0; p1[c] *= i1; }

    // scatter into A-fragment layout (verified R5 mapping)
    int ks  = T >> 3;
    int tq  = T & 3;
    int hik = ((T & 7) >= 4) ? 2 : 0;
#pragma unroll
    for (int c16 = 0; c16 < CP; c16++) {
        float a0 = 0.f, a1 = 0.f, b0 = 0.f, b1 = 0.f;
        if (c16 < NC) {
#pragma unroll
            for (int c = 0; c < NC; c++) {
                float w1 = sW1[c16 * NC + c], w2 = sW2[c16 * NC + c];
                a0 = fmaf(w1, p0[c], a0); a1 = fmaf(w1, p1[c], a1);
                b0 = fmaf(w2, p0[c], b0); b1 = fmaf(w2, p1[c], b1);
            }
        }
        int lane = (c16 & 7) * 4 + tq;
        int reg  = ((c16 >= 8) ? 1 : 0) + hik;
        __nv_bfloat162 v1 = __floats2bfloat162_rn(a0, a1);
        __nv_bfloat162 v2 = __floats2bfloat162_rn(b0, b1);
        reinterpret_cast<uint32_t*>(&g_PF[0][ks][lane])[reg] =
            *reinterpret_cast<uint32_t*>(&v1);
        reinterpret_cast<uint32_t*>(&g_PF[1][ks][lane])[reg] =
            *reinterpret_cast<uint32_t*>(&v2);
    }
}

// ---------------- symmetric GEMM ---------------------------------------------
// CTA = block pair (p<=q). Stages K[P, j-chunk] (256 x 64, both matrices) in
// swizzled smem; forward mma via ldmatrix, mirror via ldmatrix.trans.
static constexpr int SMEM_GEMM = 2 * 256 * 128;   // 64 KB

__global__ __launch_bounds__(256, 2) void k_gemm(int wbuf) {
    extern __shared__ char dyn[];
    uint32_t sb = s2u(dyn);                       // sK1
    uint32_t sb2 = sb + 256 * 128;                // sK2

    int t = threadIdx.x, w = t >> 5, lane = t & 31, g = lane >> 2, tq = lane & 3;

    // unrank pair
    int idx = blockIdx.x, p = 0;
    while (idx >= NBLK - p) { idx -= NBLK - p; p++; }
    int q = p + idx;
    bool diag = (p == q);

    float facc[4][4] = {};   // i-tiles w*4+tt (within P)
    float macc[4][4] = {};   // chunk cs -> j-tile cs*8+w (within Q)

    const char* gsp = reinterpret_cast<const char*>(g_Ksp);
    const char* gbl = reinterpret_cast<const char*>(g_Kbl);

#pragma unroll 1
    for (int cs = 0; cs < 4; cs++) {
        // ---- stage 256 x 64 of both matrices ----
        {
            int u = t & 7, rr = t >> 3;
            size_t gofs = ((size_t)(p * 256 + rr) * NPT + q * 256 + cs * 64 + u * 8) * 2;
#pragma unroll
            for (int pass = 0; pass < 8; pass++) {
                int r = rr + pass * 32;
                uint32_t so = (uint32_t)(r * 128 + ((u ^ (r & 7)) * 16));
                size_t go = gofs + (size_t)pass * 32 * NPT * 2;
                cp16(sb + so, gsp + go);
                cp16(sb2 + so, gbl + go);
            }
            cp_commit_waitall();
        }
        __syncthreads();

        // ---- forward: 2 k32 steps over this chunk's 64 j ----
        int ks0 = q * 16 + cs * 4;
#pragma unroll
        for (int kk = 0; kk < 2; kk++) {
            uint4 A1a = g_PF[0][ks0 + kk * 2][lane];
            uint4 A1b = g_PF[0][ks0 + kk * 2 + 1][lane];
            uint4 A2a = g_PF[1][ks0 + kk * 2][lane];
            uint4 A2b = g_PF[1][ks0 + kk * 2 + 1][lane];
#pragma unroll
            for (int tt = 0; tt < 4; tt++) {
                int r = (w * 4 + tt) * 8 + (lane & 7);
                int u = kk * 4 + (lane >> 3);
                uint32_t ad = (uint32_t)(r * 128 + ((u ^ (r & 7)) * 16));
                uint32_t B[4];
                ldmx4(B, sb + ad);
                mma16816(facc[tt], reinterpret_cast<const uint32_t*>(&A1a), B[0], B[1]);
                mma16816(facc[tt], reinterpret_cast<const uint32_t*>(&A1b), B[2], B[3]);
                ldmx4(B, sb2 + ad);
                mma16816(facc[tt], reinterpret_cast<const uint32_t*>(&A2a), B[0], B[1]);
                mma16816(facc[tt], reinterpret_cast<const uint32_t*>(&A2b), B[2], B[3]);
            }
        }

        // ---- mirror: j-tile (cs*8+w), k over all 256 i ----
        if (!diag) {
#pragma unroll
            for (int ik = 0; ik < 8; ik++) {
                uint4 A1a = g_PF[0][p * 16 + ik * 2][lane];
                uint4 A1b = g_PF[0][p * 16 + ik * 2 + 1][lane];
                uint4 A2a = g_PF[1][p * 16 + ik * 2][lane];
                uint4 A2b = g_PF[1][p * 16 + ik * 2 + 1][lane];
                int r = ik * 32 + (lane >> 3) * 8 + (lane & 7);
                uint32_t ad = (uint32_t)(r * 128 + ((w ^ (r & 7)) * 16));
                uint32_t B[4];
                ldmx4t(B, sb + ad);
                mma16816(macc[cs], reinterpret_cast<const uint32_t*>(&A1a), B[0], B[1]);
                mma16816(macc[cs], reinterpret_cast<const uint32_t*>(&A1b), B[2], B[3]);
                ldmx4t(B, sb2 + ad);
                mma16816(macc[cs], reinterpret_cast<const uint32_t*>(&A2a), B[0], B[1]);
                mma16816(macc[cs], reinterpret_cast<const uint32_t*>(&A2b), B[2], B[3]);
            }
        }
        __syncthreads();
    }

    // ---- epilogues ----
    float* pw = g_part[wbuf];
#pragma unroll
    for (int tt = 0; tt < 4; tt++) {
        int i = p * 256 + (w * 4 + tt) * 8 + tq * 2;
        *reinterpret_cast<float2*>(&pw[((size_t)(q * CP) + g) * NPT + i]) =
            make_float2(facc[tt][0], facc[tt][1]);
        *reinterpret_cast<float2*>(&pw[((size_t)(q * CP) + g + 8) * NPT + i]) =
            make_float2(facc[tt][2], facc[tt][3]);
    }
    if (!diag) {
#pragma unroll
        for (int cs = 0; cs < 4; cs++) {
            int j = q * 256 + (cs * 8 + w) * 8 + tq * 2;
            *reinterpret_cast<float2*>(&pw[((size_t)(p * CP) + g) * NPT + j]) =
                make_float2(macc[cs][0], macc[cs][1]);
            *reinterpret_cast<float2*>(&pw[((size_t)(p * CP) + g + 8) * NPT + j]) =
                make_float2(macc[cs][2], macc[cs][3]);
        }
    }
}

// ---------------- final output -----------------------------------------------
__global__ __launch_bounds__(128) void k_out(const float* __restrict__ unaries,
                                             float* __restrict__ out, int buf) {
    int i = blockIdx.x * 128 + threadIdx.x;
    const float* pb = g_part[buf];
#pragma unroll
    for (int c = 0; c < NC; c++) {
        float qv = unaries[(size_t)c * NPT + i];
#pragma unroll 8
        for (int sl = 0; sl < NBLK; sl++)
            qv += pb[((size_t)sl * CP + c) * NPT + i];
        out[(size_t)c * NPT + i] = qv;
    }
}

// ---------------- launch ------------------------------------------------------
extern "C" void kernel_launch(void* const* d_in, const int* in_sizes, int n_in,
                              void* d_out, int out_size) {
    const float* unaries = (const float*)d_in[0];
    const float* feat    = (const float*)d_in[1];
    const float* Wsp     = (const float*)d_in[2];
    const float* Wbl     = (const float*)d_in[3];
    const float* Comp    = (const float*)d_in[4];
    float* out = (float*)d_out;

    cudaFuncSetAttribute(k_gemm, cudaFuncAttributeMaxDynamicSharedMemorySize,
                         SMEM_GEMM);

    k_prepA<<<1, 128>>>(Wsp, Wbl, Comp);
    k_norm<<<NPT / 256, 256>>>(feat);
    k_pairs<<<dim3(64, 64), 256>>>(feat);
    for (int it = 0; it < 5; it++) {
        k_soft<<<32, 128>>>(unaries, it == 0 ? 0 : 1, (it + 1) & 1);
        k_gemm<<<NPAIR, 256, SMEM_GEMM>>>(it & 1);
    }
    k_out<<<NPT / 128, 128>>>(unaries, out, 0);
}